// round 15
// baseline (speedup 1.0000x reference)
#include <cuda_runtime.h>
#include <cuda_fp16.h>
#include <cstdint>
#include <cstddef>

static constexpr int B_  = 4;
static constexpr int N_  = 4096;
static constexpr int F_  = 256;
static constexpr int FO_ = 64;
static constexpr int TM_ = 128;    // t rows per CTA

// ---- main smem map ----
// EB1 16K @0 | EB2 16K @16384 | V 4x16K @32768 | P 3x32K @98304 | sden @196608 | eas @197120
static constexpr int EB1O = 0;
static constexpr int EB2O = 16384;
static constexpr int VO   = 32768;
static constexpr int VBUF = 16384;
static constexpr int PO   = 98304;
static constexpr int PBUF = 32768;
static constexpr int SDENO = 196608;
static constexpr int EASO  = 197120;
static constexpr int SMEM_MAIN = 198144;

// ---- prep smem: WsHi 32K | WsLo 32K | a1 256B | merge 128x66 fp32 ----
static constexpr int PWSLO = 32768;
static constexpr int PA1   = 65536;
static constexpr int PMRG  = 65792;
static constexpr int PREP_SMEM = PMRG + 128 * 66 * 4;   // 99584

__device__ float g_EA1[B_ * N_];
__device__ float g_EA2[B_ * N_];
__device__ float g_EB1[B_ * N_];
__device__ float g_EB2[B_ * N_];
__device__ float g_pm1[256];
__device__ float g_pm2[256];
__device__ __half g_Vhi[(size_t)B_ * N_ * FO_];

__device__ __forceinline__ uint32_t smem_u32(const void* p) {
    uint32_t a;
    asm("{ .reg .u64 t; cvta.to.shared.u64 t, %1; cvt.u32.u64 %0, t; }" : "=r"(a) : "l"(p));
    return a;
}
__device__ __forceinline__ uint32_t pack_hi(float a, float b) {
    uint32_t r;
    asm("prmt.b32 %0, %1, %2, 0x7632;" : "=r"(r)
        : "r"(__float_as_uint(a)), "r"(__float_as_uint(b)));
    return r;
}
__device__ __forceinline__ uint32_t pack_rnb(float a, float b) {
    uint32_t r;
    asm("cvt.rn.bf16x2.f32 %0, %1, %2;" : "=r"(r) : "f"(b), "f"(a));
    return r;
}
__device__ __forceinline__ uint32_t pack_h2(float a, float b) {
    uint32_t r;
    asm("cvt.rn.f16x2.f32 %0, %1, %2;" : "=r"(r) : "f"(b), "f"(a));
    return r;
}
__device__ __forceinline__ float trunc_bf16(float a) {
    return __uint_as_float(__float_as_uint(a) & 0xFFFF0000u);
}
__device__ __forceinline__ void ldsm4(uint32_t* r, uint32_t addr) {
    asm volatile("ldmatrix.sync.aligned.m8n8.x4.shared.b16 {%0,%1,%2,%3}, [%4];"
        : "=r"(r[0]), "=r"(r[1]), "=r"(r[2]), "=r"(r[3]) : "r"(addr));
}
__device__ __forceinline__ void ldsm4t(uint32_t* r, uint32_t addr) {
    asm volatile("ldmatrix.sync.aligned.m8n8.x4.trans.shared.b16 {%0,%1,%2,%3}, [%4];"
        : "=r"(r[0]), "=r"(r[1]), "=r"(r[2]), "=r"(r[3]) : "r"(addr));
}
__device__ __forceinline__ void mma16816h(float* c, uint32_t a0, uint32_t a1, uint32_t a2, uint32_t a3,
                                          uint32_t b0, uint32_t b1) {
    asm volatile("mma.sync.aligned.m16n8k16.row.col.f32.f16.f16.f32 "
        "{%0,%1,%2,%3}, {%4,%5,%6,%7}, {%8,%9}, {%0,%1,%2,%3};"
        : "+f"(c[0]), "+f"(c[1]), "+f"(c[2]), "+f"(c[3])
        : "r"(a0), "r"(a1), "r"(a2), "r"(a3), "r"(b0), "r"(b1));
}
__device__ __forceinline__ void mma16816b(float* c, uint32_t a0, uint32_t a1, uint32_t a2, uint32_t a3,
                                          uint32_t b0, uint32_t b1) {
    asm volatile("mma.sync.aligned.m16n8k16.row.col.f32.bf16.bf16.f32 "
        "{%0,%1,%2,%3}, {%4,%5,%6,%7}, {%8,%9}, {%0,%1,%2,%3};"
        : "+f"(c[0]), "+f"(c[1]), "+f"(c[2]), "+f"(c[3])
        : "r"(a0), "r"(a1), "r"(a2), "r"(a3), "r"(b0), "r"(b1));
}
__device__ __forceinline__ void cp16(uint32_t dst, const void* src) {
    asm volatile("cp.async.cg.shared.global [%0], [%1], 16;" :: "r"(dst), "l"(src) : "memory");
}
__device__ __forceinline__ void cp_commit() { asm volatile("cp.async.commit_group;" ::: "memory"); }
template <int NW>
__device__ __forceinline__ void cp_wait() { asm volatile("cp.async.wait_group %0;" :: "n"(NW) : "memory"); }
__device__ __forceinline__ void pref_l2(const void* p) {
    asm volatile("prefetch.global.L2 [%0];" :: "l"(p));
}

// ================= prep =================
// blocks 0..127: V = ctx@Ws (bf16 TC, kc split over 2 warp teams), fp16 V, EA
// blocks 128..383: EB (w2 inline) + per-block maxes
__global__ __launch_bounds__(512) void gat_prep(const float* __restrict__ h,
                                                const float* __restrict__ ctx,
                                                const float* __restrict__ Ws,
                                                const float* __restrict__ Wt,
                                                const float* __restrict__ a) {
    extern __shared__ char sm[];
    uint32_t smb = smem_u32(sm);
    int tid = threadIdx.x;
    int bx = blockIdx.x;
    if (bx < 128) {
        if (tid < 256) {
            int f = tid;
            const float* wr = Ws + (size_t)f * FO_;
            #pragma unroll
            for (int ch = 0; ch < 8; ch++) {
                float4 v0 = *(const float4*)(wr + ch * 8);
                float4 v1 = *(const float4*)(wr + ch * 8 + 4);
                uint4 hh = make_uint4(pack_hi(v0.x, v0.y), pack_hi(v0.z, v0.w),
                                      pack_hi(v1.x, v1.y), pack_hi(v1.z, v1.w));
                uint4 ll = make_uint4(
                    pack_rnb(v0.x - trunc_bf16(v0.x), v0.y - trunc_bf16(v0.y)),
                    pack_rnb(v0.z - trunc_bf16(v0.z), v0.w - trunc_bf16(v0.w)),
                    pack_rnb(v1.x - trunc_bf16(v1.x), v1.y - trunc_bf16(v1.y)),
                    pack_rnb(v1.z - trunc_bf16(v1.z), v1.w - trunc_bf16(v1.w)));
                uint32_t off = (uint32_t)((f * 128 + ch * 16) ^ ((f & 7) << 4));
                *(uint4*)(sm + off) = hh;
                *(uint4*)(sm + PWSLO + off) = ll;
            }
        }
        if (tid < 64) ((float*)(sm + PA1))[tid] = a[tid];
        __syncthreads();

        int l = tid & 31, w = tid >> 5;
        int team = w >> 3, wr8 = w & 7;        // 8 row-warps x 2 kc-teams
        int r1 = wr8 * 16 + (l >> 2);          // local row 0..127
        int row = bx * 128 + r1;
        int q2 = (l & 3) * 2;
        const float* cp0 = ctx + (size_t)row * F_ + q2;
        uint32_t swx = (uint32_t)((l & 7) << 4);
        uint32_t lbase = (uint32_t)((l & 15) * 128 + (l >> 4) * 16);

        float C[8][4];
        #pragma unroll
        for (int j = 0; j < 8; j++)
            #pragma unroll
            for (int i = 0; i < 4; i++) C[j][i] = 0.f;

        #pragma unroll 2
        for (int kc2 = 0; kc2 < 8; kc2++) {
            int f0 = (team * 8 + kc2) * 16;
            float2 x00 = *(const float2*)(cp0 + f0);
            float2 x10 = *(const float2*)(cp0 + 8 * F_ + f0);
            float2 x01 = *(const float2*)(cp0 + f0 + 8);
            float2 x11 = *(const float2*)(cp0 + 8 * F_ + f0 + 8);
            uint32_t ah0 = pack_hi(x00.x, x00.y), ah1 = pack_hi(x10.x, x10.y);
            uint32_t ah2 = pack_hi(x01.x, x01.y), ah3 = pack_hi(x11.x, x11.y);
            uint32_t al0 = pack_rnb(x00.x - trunc_bf16(x00.x), x00.y - trunc_bf16(x00.y));
            uint32_t al1 = pack_rnb(x10.x - trunc_bf16(x10.x), x10.y - trunc_bf16(x10.y));
            uint32_t al2 = pack_rnb(x01.x - trunc_bf16(x01.x), x01.y - trunc_bf16(x01.y));
            uint32_t al3 = pack_rnb(x11.x - trunc_bf16(x11.x), x11.y - trunc_bf16(x11.y));
            uint32_t fb = lbase + (uint32_t)(f0 * 128);
            #pragma unroll
            for (int g = 0; g < 4; g++) {
                uint32_t off = (fb + (uint32_t)(g * 32)) ^ swx;
                uint32_t bh[4], bl[4];
                ldsm4t(bh, smb + off);
                ldsm4t(bl, smb + PWSLO + off);
                mma16816b(C[2 * g],     ah0, ah1, ah2, ah3, bh[0], bh[1]);
                mma16816b(C[2 * g + 1], ah0, ah1, ah2, ah3, bh[2], bh[3]);
                mma16816b(C[2 * g],     al0, al1, al2, al3, bh[0], bh[1]);
                mma16816b(C[2 * g + 1], al0, al1, al2, al3, bh[2], bh[3]);
                mma16816b(C[2 * g],     ah0, ah1, ah2, ah3, bl[0], bl[1]);
                mma16816b(C[2 * g + 1], ah0, ah1, ah2, ah3, bl[2], bl[3]);
            }
        }

        float* mb = (float*)(sm + PMRG);   // [128][stride 66]
        if (team == 1) {
            #pragma unroll
            for (int jf = 0; jf < 8; jf++) {
                int nb = (jf >> 1) * 16 + (jf & 1) * 8 + q2;
                *(float2*)&mb[r1 * 66 + nb]       = make_float2(C[jf][0], C[jf][1]);
                *(float2*)&mb[(r1 + 8) * 66 + nb] = make_float2(C[jf][2], C[jf][3]);
            }
        }
        __syncthreads();
        if (team == 0) {
            __half* vo = g_Vhi + (size_t)row * FO_;
            const float* a1s = (const float*)(sm + PA1);
            float s0 = 0.f, s1 = 0.f;
            #pragma unroll
            for (int jf = 0; jf < 8; jf++) {
                int nb = (jf >> 1) * 16 + (jf & 1) * 8 + q2;
                float2 m0 = *(const float2*)&mb[r1 * 66 + nb];
                float2 m1 = *(const float2*)&mb[(r1 + 8) * 66 + nb];
                float c0 = C[jf][0] + m0.x, c1 = C[jf][1] + m0.y;
                float c2 = C[jf][2] + m1.x, c3 = C[jf][3] + m1.y;
                *(uint32_t*)(vo + nb)           = pack_h2(c0, c1);
                *(uint32_t*)(vo + 8 * FO_ + nb) = pack_h2(c2, c3);
                float2 av = *(const float2*)&a1s[nb];
                s0 += c0 * av.x + c1 * av.y;
                s1 += c2 * av.x + c3 * av.y;
            }
            s0 += __shfl_xor_sync(0xffffffffu, s0, 1);
            s0 += __shfl_xor_sync(0xffffffffu, s0, 2);
            s1 += __shfl_xor_sync(0xffffffffu, s1, 1);
            s1 += __shfl_xor_sync(0xffffffffu, s1, 2);
            if ((l & 3) == 0) {
                g_EA1[row] = __expf(s0);
                g_EA2[row] = __expf(0.2f * s0);
                g_EA1[row + 8] = __expf(s1);
                g_EA2[row + 8] = __expf(0.2f * s1);
            }
        }
    } else {
        float* w2s = (float*)sm;  // 256 floats
        if (tid < 256) {
            float acc = 0.f;
            const float* wr = Wt + (size_t)tid * FO_;
            #pragma unroll 8
            for (int o = 0; o < FO_; o++) acc += wr[o] * a[FO_ + o];
            w2s[tid] = acc;
        }
        __syncthreads();
        int lane = tid & 31, w = tid >> 5;   // 16 warps
        int rb = (bx - 128) * 64;
        const float4* wp = (const float4*)w2s;
        float4 w0 = wp[lane], w1 = wp[lane + 32];
        float m1 = 0.f, m2 = 0.f;
        #pragma unroll
        for (int it = 0; it < 4; it++) {
            int sg = rb + it * 16 + w;
            const float4* hp = (const float4*)(h + (size_t)sg * F_);
            float4 x0 = hp[lane], x1 = hp[lane + 32];
            float d = x0.x * w0.x + x0.y * w0.y + x0.z * w0.z + x0.w * w0.w
                    + x1.x * w1.x + x1.y * w1.y + x1.z * w1.z + x1.w * w1.w;
            #pragma unroll
            for (int off = 16; off > 0; off >>= 1) d += __shfl_xor_sync(0xffffffffu, d, off);
            if (lane == 0) {
                float e1 = __expf(d), e2 = __expf(0.2f * d);
                g_EB1[sg] = e1;
                g_EB2[sg] = e2;
                m1 = fmaxf(m1, e1);
                m2 = fmaxf(m2, e2);
            }
        }
        __syncthreads();
        float* wmx = (float*)sm;
        if (lane == 0) { wmx[w] = m1; wmx[16 + w] = m2; }
        __syncthreads();
        if (tid < 2) {
            const float* src = wmx + tid * 16;
            float m = src[0];
            #pragma unroll
            for (int i = 1; i < 16; i++) m = fmaxf(m, src[i]);
            if (tid == 0) g_pm1[bx - 128] = m;
            else          g_pm2[bx - 128] = m;
        }
    }
}

// ================= main =================
// 16 warps. P-gen: warp w owns rows 8w..8w+7 (coalesced adj), P -> smem (swizzled).
// mma: warp (wm,kh): rows wm*32..+32, s-quarter kh*32..+32, A via ldsm from P.
// V ring has FOUR slots: in any barrier window, fills target slot s+3 while
// straggler mma reads slot s (distance 3 mod 4 != 0 -> no race; mod 3 raced).
__global__ __launch_bounds__(512, 1)
void gat_main(const int* __restrict__ adj, float* __restrict__ out) {
    extern __shared__ char sm[];
    uint32_t smb = smem_u32(sm);
    float* EB1s = (float*)(sm + EB1O);
    float* EB2s = (float*)(sm + EB2O);
    float* sden = (float*)(sm + SDENO);          // [128]
    const float2* eas2 = (const float2*)(sm + EASO);

    int tid = threadIdx.x;
    int l = tid & 31, wid = tid >> 5;
    int cta = blockIdx.x;
    int b = cta >> 5;
    int t0 = (cta & 31) * TM_;
    int bN = b * N_;
    int wm = wid & 3;
    int kh = wid >> 2;

    // ---- prologue: stage EB, pm; compute mB; compute scaled eas ----
    {
        const float4* s1 = (const float4*)(g_EB1 + bN);
        const float4* s2 = (const float4*)(g_EB2 + bN);
        float4* d1 = (float4*)EB1s;
        float4* d2 = (float4*)EB2s;
        d1[tid] = s1[tid]; d1[tid + 512] = s1[tid + 512];
        d2[tid] = s2[tid]; d2[tid + 512] = s2[tid + 512];
        float* stg = (float*)(sm + PO);
        if (tid < 64) {
            stg[tid]      = g_pm1[b * 64 + tid];
            stg[64 + tid] = g_pm2[b * 64 + tid];
        }
    }
    __syncthreads();
    {
        const float* stg = (const float*)(sm + PO);
        float mB1 = stg[0], mB2 = stg[64];
        #pragma unroll
        for (int i = 1; i < 64; i++) {
            mB1 = fmaxf(mB1, stg[i]);
            mB2 = fmaxf(mB2, stg[64 + i]);
        }
        if (tid < 128) {
            float e1 = g_EA1[bN + t0 + tid];
            float e2 = g_EA2[bN + t0 + tid];
            float M = fmaxf(e1 * mB1, e2 * mB2);
            uint32_t eb = (__float_as_uint(M) >> 23) & 0xFFu;
            float s = __uint_as_float((267u - eb) << 23);   // scaled bound in [2^13, 2^14)
            ((float2*)(sm + EASO))[tid] = make_float2(e1 * s, e2 * s);
        }
    }

    // fill-side mappings
    const int* adjW = adj + (size_t)(bN + t0 + 8 * wid) * N_;   // warp's 8 rows
    int vr2 = tid >> 2, vq = tid & 3;
    uint32_t p0 = (uint32_t)(vq * 32) ^ ((uint32_t)(vr2 & 7) << 4);
    uint32_t p1 = (uint32_t)(vq * 32 + 16) ^ ((uint32_t)(vr2 & 7) << 4);
    uint32_t vrow = (uint32_t)(vr2 * 128);
    const char* vsh = (const char*)(g_Vhi + ((size_t)bN + vr2) * FO_) + vq * 32;

    // mma-side geometry
    uint32_t lbB = (uint32_t)((kh * 32 + (l & 15)) * 128 + (l >> 4) * 16);
    uint32_t swx = (uint32_t)((l & 7) << 4);
    uint32_t lbA = (uint32_t)((wm * 32 + (l & 15)) * 256);
    uint32_t cbA = (uint32_t)(kh * 64 + (l >> 4) * 16);
    uint32_t pwoff = (uint32_t)(wid * 8 * 256);   // P-gen warp row base (bytes)

    // V(0) fill
    {
        uint32_t d = smb + VO + vrow;
        cp16(d + p0, vsh);
        cp16(d + p1, vsh + 16);
        cp_commit();
    }
    __syncthreads();   // eas/EB ready

    float C0[8][4], C1[8][4];
    #pragma unroll
    for (int f = 0; f < 8; f++)
        #pragma unroll
        for (int i = 0; i < 4; i++) { C0[f][i] = 0.f; C1[f][i] = 0.f; }
    float dd[8] = {0.f, 0.f, 0.f, 0.f, 0.f, 0.f, 0.f, 0.f};

    int pcur = 0;   // i % 3
    int pprev = 2;  // (i-1) % 3
    for (int i = 0; i <= 32; i++) {
        // V fill for i+1 (4-slot ring) and adj L2 prefetch
        if (i < 31) {
            uint32_t d = smb + VO + (uint32_t)(((i + 1) & 3) * VBUF) + vrow;
            const char* s = vsh + (size_t)(i + 1) * 16384;
            cp16(d + p0, s);
            cp16(d + p1, s + 16);
            cp_commit();
            {
                const int* pf = adjW + (size_t)(l >> 2) * N_ + (i + 1) * 128 + (l & 3) * 32;
                pref_l2(pf);
            }
        }
        // P-gen(i)
        if (i < 32) {
            uint32_t pw = PO + (uint32_t)(pcur * PBUF) + pwoff;
            #pragma unroll
            for (int cc = 0; cc < 2; cc++) {
                int sc = i * 128 + cc * 64 + 2 * l;
                int2 av[8];
                #pragma unroll
                for (int r = 0; r < 8; r++)
                    av[r] = *(const int2*)(adjW + (size_t)r * N_ + sc);
                float2 e1 = *(const float2*)&EB1s[sc];
                float2 e2 = *(const float2*)&EB2s[sc];
                #pragma unroll
                for (int r = 0; r < 8; r++) {
                    float2 ea = eas2[8 * wid + r];
                    float x0 = fmaxf(ea.x * e1.x, ea.y * e2.x); x0 = (av[r].x > 0) ? x0 : 0.f;
                    float x1 = fmaxf(ea.x * e1.y, ea.y * e2.y); x1 = (av[r].y > 0) ? x1 : 0.f;
                    dd[r] += x0 + x1;
                    uint32_t pos = ((uint32_t)(cc * 128 + l * 4)) ^ ((uint32_t)r << 4);
                    *(uint32_t*)(sm + pw + (uint32_t)(r * 256) + pos) = pack_h2(x0, x1);
                }
            }
        }
        // wait V, barrier, mma(i-1)
        if (i < 31)      cp_wait<2>();
        else if (i == 31) cp_wait<1>();
        else             cp_wait<0>();
        __syncthreads();
        if (i >= 1) {
            int im1 = i - 1;
            uint32_t pbm = smb + PO + (uint32_t)(pprev * PBUF);
            uint32_t vb = smb + VO + (uint32_t)((im1 & 3) * VBUF);
            #pragma unroll
            for (int kk = 0; kk < 2; kk++) {
                uint32_t acol = (cbA + (uint32_t)(kk * 32)) ^ swx;
                uint32_t a0[4], a1r[4];
                ldsm4(a0,  pbm + lbA + acol);
                ldsm4(a1r, pbm + lbA + 4096 + acol);
                uint32_t ob = lbB + (uint32_t)(kk * 2048);
                #pragma unroll
                for (int ng = 0; ng < 4; ng++) {
                    uint32_t off = (ob + (uint32_t)(ng * 32)) ^ swx;
                    uint32_t bh[4];
                    ldsm4t(bh, vb + off);
                    mma16816h(C0[2 * ng],     a0[0], a0[1], a0[2], a0[3], bh[0], bh[1]);
                    mma16816h(C0[2 * ng + 1], a0[0], a0[1], a0[2], a0[3], bh[2], bh[3]);
                    mma16816h(C1[2 * ng],     a1r[0], a1r[1], a1r[2], a1r[3], bh[0], bh[1]);
                    mma16816h(C1[2 * ng + 1], a1r[0], a1r[1], a1r[2], a1r[3], bh[2], bh[3]);
                }
            }
        }
        pprev = pcur;
        pcur = (pcur == 2) ? 0 : pcur + 1;
    }

    // ---- epilogue ----
    __syncthreads();   // all mma done before merge-area writes
    #pragma unroll
    for (int r = 0; r < 8; r++) {
        float v = dd[r];
        v += __shfl_xor_sync(0xffffffffu, v, 16);
        v += __shfl_xor_sync(0xffffffffu, v, 8);
        v += __shfl_xor_sync(0xffffffffu, v, 4);
        v += __shfl_xor_sync(0xffffffffu, v, 2);
        v += __shfl_xor_sync(0xffffffffu, v, 1);
        if (l == 0) sden[8 * wid + r] = v;
    }
    int cb = (l & 3) * 2;
    if (kh) {
        float* mb = (float*)sm + (size_t)(kh - 1) * 8192;
        #pragma unroll
        for (int g = 0; g < 2; g++) {
            int rr = wm * 32 + g * 16 + (l >> 2);
            float (*Cg)[4] = g ? C1 : C0;
            #pragma unroll
            for (int f = 0; f < 8; f++) {
                *(float2*)&mb[rr * 64 + f * 8 + cb]       = make_float2(Cg[f][0], Cg[f][1]);
                *(float2*)&mb[(rr + 8) * 64 + f * 8 + cb] = make_float2(Cg[f][2], Cg[f][3]);
            }
        }
    }
    __syncthreads();
    if (kh == 0) {
        const float* m1 = (const float*)sm;
        const float* m2 = m1 + 8192;
        const float* m3 = m2 + 8192;
        #pragma unroll
        for (int g = 0; g < 2; g++) {
            int rr = wm * 32 + g * 16 + (l >> 2);
            float rd0 = 1.f / sden[rr];
            int rs = rr + 8;
            float rd1 = 1.f / sden[rs];
            float (*Cg)[4] = g ? C1 : C0;
            float* o0 = out + (size_t)(bN + t0 + rr) * FO_ + cb;
            float* o1 = out + (size_t)(bN + t0 + rs) * FO_ + cb;
            #pragma unroll
            for (int f = 0; f < 8; f++) {
                int i0 = rr * 64 + f * 8 + cb, i1 = rs * 64 + f * 8 + cb;
                float x0 = (Cg[f][0] + m1[i0] + m2[i0] + m3[i0]) * rd0;
                float x1 = (Cg[f][1] + m1[i0 + 1] + m2[i0 + 1] + m3[i0 + 1]) * rd0;
                float x2 = (Cg[f][2] + m1[i1] + m2[i1] + m3[i1]) * rd1;
                float x3 = (Cg[f][3] + m1[i1 + 1] + m2[i1 + 1] + m3[i1 + 1]) * rd1;
                x0 = (x0 > 0.f) ? x0 : 0.01f * x0;
                x1 = (x1 > 0.f) ? x1 : 0.01f * x1;
                x2 = (x2 > 0.f) ? x2 : 0.01f * x2;
                x3 = (x3 > 0.f) ? x3 : 0.01f * x3;
                *(float2*)o0 = make_float2(x0, x1);
                *(float2*)o1 = make_float2(x2, x3);
                o0 += 8; o1 += 8;
            }
        }
    }
}

// ---------------- launcher ----------------
extern "C" void kernel_launch(void* const* d_in, const int* in_sizes, int n_in,
                              void* d_out, int out_size) {
    const float* h   = (const float*)d_in[0];
    const float* ctx = (const float*)d_in[1];
    const int*   adj = (const int*)d_in[2];
    const float* Ws  = (const float*)d_in[3];
    const float* Wt  = (const float*)d_in[4];
    const float* a   = (const float*)d_in[5];
    float* out = (float*)d_out;

    cudaFuncSetAttribute(gat_prep, cudaFuncAttributeMaxDynamicSharedMemorySize, PREP_SMEM);
    cudaFuncSetAttribute(gat_main, cudaFuncAttributeMaxDynamicSharedMemorySize, SMEM_MAIN);

    gat_prep<<<384, 512, PREP_SMEM>>>(h, ctx, Ws, Wt, a);
    gat_main<<<B_ * (N_ / TM_), 512, SMEM_MAIN>>>(adj, out);
}